// round 13
// baseline (speedup 1.0000x reference)
#include <cuda_runtime.h>
#include <cstdint>

#define BT 1024
#define NB 4096
#define ESTR 336   // smem bytes per element (320 used + 16 pad for 3-elem/warp banks)

typedef unsigned long long u64;

__device__ __forceinline__ u64 pk2(float lo, float hi) {
    u64 r; asm("mov.b64 %0, {%1,%2};" : "=l"(r) : "f"(lo), "f"(hi)); return r;
}
__device__ __forceinline__ void unpk2(u64 p, float& lo, float& hi) {
    asm("mov.b64 {%0,%1}, %2;" : "=f"(lo), "=f"(hi) : "l"(p));
}
__device__ __forceinline__ u64 ffma2(u64 a, u64 b, u64 c) {
    u64 d; asm("fma.rn.f32x2 %0, %1, %2, %3;" : "=l"(d) : "l"(a), "l"(b), "l"(c)); return d;
}
__device__ __forceinline__ u64 fmul2(u64 a, u64 b) {
    u64 d; asm("mul.rn.f32x2 %0, %1, %2;" : "=l"(d) : "l"(a), "l"(b)); return d;
}
__device__ __forceinline__ u64 fadd2(u64 a, u64 b) {
    u64 d; asm("add.rn.f32x2 %0, %1, %2;" : "=l"(d) : "l"(a), "l"(b)); return d;
}
__device__ __forceinline__ float ex2f(float x) {
    float y; asm("ex2.approx.f32 %0, %1;" : "=f"(y) : "f"(x)); return y;
}
__device__ __forceinline__ float rcpf(float x) {
    float y; asm("rcp.approx.f32 %0, %1;" : "=f"(y) : "f"(x)); return y;
}

// Reduction-dim f32x2 packed weights, gate scales pre-folded (i/f/o: -log2e, g: +2log2e).
struct CellW { u64 WA[4][3], WB[4][3], BA[4]; };

// Fused-activation LSTM cell (5 EX2 + 3 RCP):
//   i*g = (Eg-1)*rcp((Eg+1)(Ei+1));  f*c = c*rcp(Ef+1)
//   h   = (Ec-1)*rcp((Ec+1)(Eo+1)),  Ec = ex2(min(2log2e*c, 100))
__device__ __forceinline__ void cell(const CellW& w, const u64* A, const u64* Bp,
                                     float cin, float& cn, float& hn)
{
    float z[4];
#pragma unroll
    for (int q = 0; q < 4; ++q) {
        u64 a = ffma2(w.WA[q][0], A[0], w.BA[q]);
        a = ffma2(w.WA[q][1], A[1], a);
        a = ffma2(w.WA[q][2], A[2], a);
        u64 bb = fmul2(w.WB[q][0], Bp[0]);
        bb = ffma2(w.WB[q][1], Bp[1], bb);
        bb = ffma2(w.WB[q][2], Bp[2], bb);
        a = fadd2(a, bb);
        float lo, hi; unpk2(a, lo, hi);
        z[q] = lo + hi;
    }
    float Ei = ex2f(z[0]), Ef = ex2f(z[1]), Eg = ex2f(z[2]), Eo = ex2f(z[3]);
    float ig = (Eg - 1.0f) * rcpf((Eg + 1.0f) * (Ei + 1.0f));
    cn = fmaf(cin, rcpf(Ef + 1.0f), ig);
    float zc = fminf(cn * 2.8853900817779268f, 100.0f);
    float Ec = ex2f(zc);
    hn = (Ec - 1.0f) * rcpf((Ec + 1.0f) * (Eo + 1.0f));
}

// smem per element (ESTR bytes):
//   A region [0,192): 4 slots*48B; slot s: [0,24)=x[t], [24,48)=h0[t-1]
//   B region [192,288): 2 slots*48B; slot s: [0,24)=h0, [24,48)=h1
// Body t: layer0 lanes -> h0[t], layer1 lanes -> h1[t-1] (stored to gmem).
// x staging: body t LDGs x[t+5] (1 u64/stager lane), STSs x[t+3] (LDG'd 2 bodies ago).
// Exchange is CTA-wide (8 elements / 96 threads) via __syncthreads().

#define BODY(TP,BR,BW,AH,XS,Q,LDI,STI,DOLDG,DOSTSX,DOSTG) do {               \
    u64 A_[3], B_[3];                                                        \
    A_[0] = *(const u64*)(a_base  + (TP)*48 + 0);                            \
    A_[1] = *(const u64*)(a_base  + (TP)*48 + 8);                            \
    A_[2] = *(const u64*)(a_base  + (TP)*48 + 16);                           \
    B_[0] = *(const u64*)(bb_base + (BR)*48 + 0);                            \
    B_[1] = *(const u64*)(bb_base + (BR)*48 + 8);                            \
    B_[2] = *(const u64*)(bb_base + (BR)*48 + 16);                           \
    float cn_, hn_;                                                          \
    cell(W, A_, B_, c, cn_, hn_);                                            \
    c = cn_; h = hn_;                                                        \
    if ((DOSTG) && is_l1) og_run[(STI)] = hn_;                               \
    *(float*)(hst_base + (BW)*48) = h;                                       \
    if (!is_l1) *(float*)(h0st_base + (AH)*48) = h;                          \
    if ((DOSTSX) && stager) *(u64*)(xst_base + (XS)*48) = xq[(Q)];           \
    if ((DOLDG)  && stager) xq[(Q)] = __ldg(xg_run + (LDI));                 \
    __syncthreads();                                                         \
} while (0)

__global__ void __launch_bounds__(96)
lstm2_kernel(const float* __restrict__ x,
             const float* __restrict__ wih0, const float* __restrict__ whh0,
             const float* __restrict__ bih0, const float* __restrict__ bhh0,
             const float* __restrict__ wih1, const float* __restrict__ whh1,
             const float* __restrict__ bih1, const float* __restrict__ bhh1,
             float* __restrict__ out)
{
    __shared__ __align__(16) char sm[8 * ESTR];

    const int tid = threadIdx.x;          // 96 threads = 8 elements * 12 lanes
    const int ei  = tid / 12;             // element slot in CTA (0..7)
    const int r   = tid % 12;
    const bool is_l1 = (r >= 6);          // lanes 0-5: layer0, 6-11: layer1
    const int j = r % 6;                  // hidden unit
    const int b = blockIdx.x * 8 + ei;    // 512 CTAs * 8 = 4096 exact
    const bool stager = (!is_l1) && (j < 3);   // 3 lanes stage x (1 u64 each)

    char* elem      = sm + ei * ESTR;
    char* a_base    = elem + (is_l1 ? 24 : 0);            // + TP*48 + m*8
    char* bb_base   = elem + 192 + (is_l1 ? 24 : 0);      // + BR*48 + m*8
    char* hst_base  = elem + 192 + r * 4;                 // + BW*48
    char* h0st_base = elem + 24 + j * 4;                  // + AH*48 (layer0 only)
    char* xst_base  = elem + j * 8;                       // + XS*48 (stagers only)

    const float SSIG = -1.4426950408889634f;   // -log2(e)
    const float SGc  =  2.8853900817779268f;   //  2*log2(e)

    const float* Wih = is_l1 ? wih1 : wih0;
    const float* Whh = is_l1 ? whh1 : whh0;
    const float* Bih = is_l1 ? bih1 : bih0;
    const float* Bhh = is_l1 ? bhh1 : bhh0;

    CellW W;
#pragma unroll
    for (int q = 0; q < 4; ++q) {              // q: 0=i 1=f 2=g 3=o
        const int row = j + 6 * q;
        const float s = (q == 2) ? SGc : SSIG;
#pragma unroll
        for (int m = 0; m < 3; ++m) {
            W.WA[q][m] = pk2(Wih[row * 6 + 2 * m] * s, Wih[row * 6 + 2 * m + 1] * s);
            W.WB[q][m] = pk2(Whh[row * 6 + 2 * m] * s, Whh[row * 6 + 2 * m + 1] * s);
        }
        W.BA[q] = pk2((Bih[row] + Bhh[row]) * s, 0.0f);
    }

    const u64* xg_run = (const u64*)(x + (size_t)b * (BT * 6)) + j;  // u64 idx t*3+j
    float* og_run = out + (size_t)b * (BT * 6) + j;
    float h = 0.f, c = 0.f;
    u64 xq[2] = {0ull, 0ull};

    // ---- prologue: zero init slots, stage x[0..2], prime xq with x[3],x[4] ----
    *(float*)(hst_base + 48) = 0.f;                 // B slot1 = h[-1] = 0
    if (!is_l1) *(float*)(h0st_base + 0) = 0.f;     // A slot0 h0 (body0 l1, discarded)
    if (stager) {
        *(u64*)(xst_base + 0 * 48) = __ldg(xg_run + 0);
        *(u64*)(xst_base + 1 * 48) = __ldg(xg_run + 3);
        *(u64*)(xst_base + 2 * 48) = __ldg(xg_run + 6);
        xq[0] = __ldg(xg_run + 9);    // x[3]
        xq[1] = __ldg(xg_run + 12);   // x[4]
    }
    __syncthreads();

    // ---- peel t=0: commit layer0 only (layer1 result discarded), no STG ----
    {
        u64 A_[3], B_[3];
        A_[0] = *(const u64*)(a_base + 0);
        A_[1] = *(const u64*)(a_base + 8);
        A_[2] = *(const u64*)(a_base + 16);
        B_[0] = *(const u64*)(bb_base + 48 + 0);
        B_[1] = *(const u64*)(bb_base + 48 + 8);
        B_[2] = *(const u64*)(bb_base + 48 + 16);
        float cn_, hn_;
        cell(W, A_, B_, c, cn_, hn_);
        if (!is_l1) { c = cn_; h = hn_; }
        *(float*)(hst_base + 0) = h;                       // BW=0
        if (!is_l1) *(float*)(h0st_base + 48) = h;         // AH=1
        if (stager) {
            *(u64*)(xst_base + 3 * 48) = xq[0];            // x[3] -> slot 3
            xq[0] = __ldg(xg_run + 15);                    // x[5]
        }
        __syncthreads();
    }
    xg_run += 3;   // t_base = 1

    // ---- main: t = 1..1016 (254 groups of 4); all immediates compile-time ----
#pragma unroll 1
    for (int g = 0; g < 254; ++g) {
        //   TP BR BW AH XS Q  LDI STI
        BODY(1, 0, 1, 2, 0, 1, 15,  0, true, true, true);   // t%4==1
        BODY(2, 1, 0, 3, 1, 0, 18,  6, true, true, true);   // t%4==2
        BODY(3, 0, 1, 0, 2, 1, 21, 12, true, true, true);   // t%4==3
        BODY(0, 1, 0, 1, 3, 0, 24, 18, true, true, true);   // t%4==0
        xg_run += 12;
        og_run += 24;
    }

    // ---- tail: t = 1017..1023 (xg_run at t_base=1017, og_run at out[1016*6]) ----
    BODY(1, 0, 1, 2, 0, 1, 15,  0, true,  true,  true);   // t=1017: LDG x[1022], STS x[1020]
    BODY(2, 1, 0, 3, 1, 0, 18,  6, true,  true,  true);   // t=1018: LDG x[1023], STS x[1021]
    BODY(3, 0, 1, 0, 2, 1,  0, 12, false, true,  true);   // t=1019: STS x[1022]
    BODY(0, 1, 0, 1, 3, 0,  0, 18, false, true,  true);   // t=1020: STS x[1023]
    BODY(1, 0, 1, 2, 0, 1,  0, 24, false, false, true);   // t=1021
    BODY(2, 1, 0, 3, 1, 0,  0, 30, false, false, true);   // t=1022
    BODY(3, 0, 1, 0, 2, 1,  0, 36, false, false, true);   // t=1023

    // ---- epilogue t=1024: layer1 computes & stores h1[1023] ----
    {
        u64 A_[3], B_[3];
        A_[0] = *(const u64*)(a_base + 0);                 // slot0: h0[1023] for l1
        A_[1] = *(const u64*)(a_base + 8);
        A_[2] = *(const u64*)(a_base + 16);
        B_[0] = *(const u64*)(bb_base + 48 + 0);           // slot1: h[1023]
        B_[1] = *(const u64*)(bb_base + 48 + 8);
        B_[2] = *(const u64*)(bb_base + 48 + 16);
        float cn_, hn_;
        cell(W, A_, B_, c, cn_, hn_);
        if (is_l1) og_run[42] = hn_;                       // out[1023*6 + j]
    }
}

extern "C" void kernel_launch(void* const* d_in, const int* in_sizes, int n_in,
                              void* d_out, int out_size)
{
    const float* x    = (const float*)d_in[0];
    const float* wih0 = (const float*)d_in[1];
    const float* whh0 = (const float*)d_in[2];
    const float* bih0 = (const float*)d_in[3];
    const float* bhh0 = (const float*)d_in[4];
    const float* wih1 = (const float*)d_in[5];
    const float* whh1 = (const float*)d_in[6];
    const float* bih1 = (const float*)d_in[7];
    const float* bhh1 = (const float*)d_in[8];
    float* out = (float*)d_out;

    // 4096 elements, 8 per CTA (96 threads = 3 full warps, zero idle lanes)
    lstm2_kernel<<<512, 96>>>(x, wih0, whh0, bih0, bhh0,
                              wih1, whh1, bih1, bhh1, out);
}